// round 1
// baseline (speedup 1.0000x reference)
#include <cuda_runtime.h>
#include <math.h>
#include <stdint.h>

#define BB 64
#define LL 128
#define TT 48
#define EE 512
#define HEE 1024
#define HH 1024

// ---------------- device scratch (no allocations allowed) ----------------
__device__ float g_enc_proj[BB * LL * HH];        // 32 MB
__device__ float g_gates[4 * BB * 4 * HH];        // 4 partials x (B,4H)
__device__ float g_comb[8 * BB * HH];             // 8 partials x (B,H)
__device__ float g_h1[BB * HH];
__device__ float g_c1[BB * HH];
__device__ float g_h2[BB * HH];
__device__ float g_c2[BB * HH];
__device__ float g_o0[BB * HH];
__device__ float g_e[BB * LL];
__device__ float g_alpha[BB * LL];
__device__ float g_at[BB * HEE];

// ---------------- init: copy states, zero o0 ----------------
__global__ void init_k(const float* __restrict__ h1i, const float* __restrict__ c1i,
                       const float* __restrict__ h2i, const float* __restrict__ c2i) {
    int i = blockIdx.x * 256 + threadIdx.x;
    if (i < BB * HH) {
        g_h1[i] = h1i[i];
        g_c1[i] = c1i[i];
        g_h2[i] = h2i[i];
        g_c2[i] = c2i[i];
        g_o0[i] = 0.f;
    }
}

// ---------------- generic multi-pair GEMM: C = sum_p A_p @ W_p^T (+bias) ----------------
// Tiles: 64(M) x 64(N) x 32(K). 256 threads, 4x4 per thread.
// mode 0: direct store (+bias).  mode 2: partial store to C + z*zstride (bias only at z==0).
__global__ __launch_bounds__(256) void gemm_mp(
    const float* __restrict__ A0, int lda0, const float* __restrict__ W0, int ldw0, int K0,
    const float* __restrict__ A1, int lda1, const float* __restrict__ W1, int ldw1, int K1,
    const float* __restrict__ A2, int lda2, const float* __restrict__ W2, int ldw2, int K2,
    const float* __restrict__ bias0, const float* __restrict__ bias1,
    float* __restrict__ C, int ldc, int zstride, int ksplit, int mode)
{
    __shared__ float As[64][33];
    __shared__ float Ws[64][33];

    const int tid = threadIdx.x;
    const int tx = tid & 15;
    const int ty = tid >> 4;
    const int n0 = blockIdx.x * 64;
    const int m0 = blockIdx.y * 64;
    const int z  = blockIdx.z;

    float acc[4][4];
#pragma unroll
    for (int i = 0; i < 4; ++i)
#pragma unroll
        for (int j = 0; j < 4; ++j) acc[i][j] = 0.f;

    const float* Ap[3] = {A0, A1, A2};
    const float* Wp[3] = {W0, W1, W2};
    const int ldap[3]  = {lda0, lda1, lda2};
    const int ldwp[3]  = {ldw0, ldw1, ldw2};
    const int Kp[3]    = {K0, K1, K2};

    for (int p = 0; p < 3; ++p) {
        const float* A = Ap[p];
        if (A == nullptr) continue;
        const float* W = Wp[p];
        const int lda = ldap[p];
        const int ldw = ldwp[p];
        const int Kpart = Kp[p] / ksplit;
        const int kbase = z * Kpart;

        for (int kt = 0; kt < Kpart; kt += 32) {
            // load 64x32 tiles of A and W (float4, coalesced)
#pragma unroll
            for (int u = 0; u < 2; ++u) {
                int id = tid + u * 256;          // 0..511
                int row = id >> 3;               // 0..63
                int kq = (id & 7) << 2;          // 0,4,...,28
                const float4 av = *reinterpret_cast<const float4*>(
                    &A[(size_t)(m0 + row) * lda + kbase + kt + kq]);
                const float4 wv = *reinterpret_cast<const float4*>(
                    &W[(size_t)(n0 + row) * ldw + kbase + kt + kq]);
                As[row][kq + 0] = av.x; As[row][kq + 1] = av.y;
                As[row][kq + 2] = av.z; As[row][kq + 3] = av.w;
                Ws[row][kq + 0] = wv.x; Ws[row][kq + 1] = wv.y;
                Ws[row][kq + 2] = wv.z; Ws[row][kq + 3] = wv.w;
            }
            __syncthreads();
#pragma unroll
            for (int kk = 0; kk < 32; ++kk) {
                float a0 = As[ty * 4 + 0][kk];
                float a1 = As[ty * 4 + 1][kk];
                float a2 = As[ty * 4 + 2][kk];
                float a3 = As[ty * 4 + 3][kk];
                float w0 = Ws[tx * 4 + 0][kk];
                float w1 = Ws[tx * 4 + 1][kk];
                float w2 = Ws[tx * 4 + 2][kk];
                float w3 = Ws[tx * 4 + 3][kk];
                acc[0][0] += a0 * w0; acc[0][1] += a0 * w1; acc[0][2] += a0 * w2; acc[0][3] += a0 * w3;
                acc[1][0] += a1 * w0; acc[1][1] += a1 * w1; acc[1][2] += a1 * w2; acc[1][3] += a1 * w3;
                acc[2][0] += a2 * w0; acc[2][1] += a2 * w1; acc[2][2] += a2 * w2; acc[2][3] += a2 * w3;
                acc[3][0] += a3 * w0; acc[3][1] += a3 * w1; acc[3][2] += a3 * w2; acc[3][3] += a3 * w3;
            }
            __syncthreads();
        }
    }

#pragma unroll
    for (int i = 0; i < 4; ++i) {
        const int m = m0 + ty * 4 + i;
#pragma unroll
        for (int j = 0; j < 4; ++j) {
            const int n = n0 + tx * 4 + j;
            float v = acc[i][j];
            if (mode == 2) {
                if (z == 0) {
                    if (bias0) v += bias0[n];
                    if (bias1) v += bias1[n];
                }
                C[(size_t)z * zstride + (size_t)m * ldc + n] = v;
            } else {
                if (bias0) v += bias0[n];
                if (bias1) v += bias1[n];
                C[(size_t)m * ldc + n] = v;
            }
        }
    }
}

// ---------------- LSTM pointwise (sums ksplit partials) ----------------
__global__ void lstm_pw(const float* __restrict__ gates, int ksplit,
                        float* __restrict__ h, float* __restrict__ c) {
    const int idx = blockIdx.x * 256 + threadIdx.x;  // B*H
    const int b = idx >> 10;
    const int hh = idx & (HH - 1);
    float gi = 0.f, gf = 0.f, gg = 0.f, go = 0.f;
    for (int zz = 0; zz < ksplit; ++zz) {
        const float* g = gates + (size_t)zz * BB * 4 * HH + (size_t)b * 4 * HH + hh;
        gi += g[0];
        gf += g[HH];
        gg += g[2 * HH];
        go += g[3 * HH];
    }
    const float i_g = 1.f / (1.f + __expf(-gi));
    const float f_g = 1.f / (1.f + __expf(-gf));
    const float g_g = tanhf(gg);
    const float o_g = 1.f / (1.f + __expf(-go));
    const float cn = f_g * c[idx] + i_g * g_g;
    c[idx] = cn;
    h[idx] = o_g * tanhf(cn);
}

// ---------------- attention scores: e[b,l] = <h2[b], enc_proj[b,l]> (masked) ----------------
__global__ void scores_k(const float* __restrict__ h2, const int* __restrict__ masks,
                         const float* __restrict__ encproj, float* __restrict__ e) {
    const int b = blockIdx.y;
    const int l0 = blockIdx.x * 16;
    __shared__ float sh[HH];
    for (int k = threadIdx.x; k < HH; k += 256) sh[k] = h2[b * HH + k];
    __syncthreads();
    const int warp = threadIdx.x >> 5;
    const int lane = threadIdx.x & 31;
#pragma unroll
    for (int li = 0; li < 2; ++li) {
        const int l = l0 + warp * 2 + li;
        const float* ep = encproj + ((size_t)b * LL + l) * HH;
        float s = 0.f;
#pragma unroll 4
        for (int k = lane; k < HH; k += 32) s += sh[k] * ep[k];
#pragma unroll
        for (int o = 16; o; o >>= 1) s += __shfl_xor_sync(0xffffffffu, s, o);
        if (lane == 0) e[b * LL + l] = masks[b * LL + l] ? -1e30f : s;
    }
}

// ---------------- softmax over L=128 ----------------
__global__ void softmax_k(const float* __restrict__ e, float* __restrict__ alpha) {
    const int b = blockIdx.x;
    const int t = threadIdx.x;  // 128
    __shared__ float sv[LL];
    const float v = e[b * LL + t];
    sv[t] = v;
    __syncthreads();
    for (int s = 64; s; s >>= 1) {
        if (t < s) sv[t] = fmaxf(sv[t], sv[t + s]);
        __syncthreads();
    }
    const float mx = sv[0];
    __syncthreads();
    const float p = __expf(v - mx);
    sv[t] = p;
    __syncthreads();
    for (int s = 64; s; s >>= 1) {
        if (t < s) sv[t] += sv[t + s];
        __syncthreads();
    }
    alpha[b * LL + t] = p / sv[0];
}

// ---------------- attention output: a[b,f] = sum_l alpha[b,l]*enc[b,l,f] ----------------
__global__ void attnout_k(const float* __restrict__ alpha, const float* __restrict__ enc,
                          float* __restrict__ a) {
    const int b = blockIdx.y;
    const int f = blockIdx.x * 128 + threadIdx.x;
    __shared__ float sa[LL];
    sa[threadIdx.x] = alpha[b * LL + threadIdx.x];  // blockDim == 128 == LL
    __syncthreads();
    float acc = 0.f;
    const float* ep = enc + (size_t)b * LL * HEE + f;
#pragma unroll 8
    for (int l = 0; l < LL; ++l) acc += sa[l] * ep[(size_t)l * HEE];
    a[b * HEE + f] = acc;
}

// ---------------- combined-output finish: out = tanh(sum_z partial) ----------------
__global__ void finish_k(const float* __restrict__ comb, int ksplit, float* __restrict__ out) {
    const int idx = blockIdx.x * 256 + threadIdx.x;  // B*H
    float v = 0.f;
    for (int zz = 0; zz < ksplit; ++zz) v += comb[(size_t)zz * BB * HH + idx];
    out[idx] = tanhf(v);
}

// ---------------- host launcher ----------------
extern "C" void kernel_launch(void* const* d_in, const int* in_sizes, int n_in,
                              void* d_out, int out_size) {
    const float* enc    = (const float*)d_in[0];
    const int*   masks  = (const int*)d_in[1];
    const float* h1i    = (const float*)d_in[2];
    const float* c1i    = (const float*)d_in[3];
    const float* h2i    = (const float*)d_in[4];
    const float* c2i    = (const float*)d_in[5];
    const float* cap    = (const float*)d_in[6];
    const float* W_ih1  = (const float*)d_in[7];
    const float* W_hh1  = (const float*)d_in[8];
    const float* b_ih1  = (const float*)d_in[9];
    const float* b_hh1  = (const float*)d_in[10];
    const float* W_ih2  = (const float*)d_in[11];
    const float* W_hh2  = (const float*)d_in[12];
    const float* b_ih2  = (const float*)d_in[13];
    const float* b_hh2  = (const float*)d_in[14];
    const float* W_att  = (const float*)d_in[15];
    const float* b_att  = (const float*)d_in[16];
    const float* W_comb = (const float*)d_in[17];
    const float* b_comb = (const float*)d_in[18];
    float* outs = (float*)d_out;  // (T, B, H)

    float *p_encproj, *p_gates, *p_comb, *p_h1, *p_c1, *p_h2, *p_c2, *p_o0, *p_e, *p_alpha, *p_at;
    cudaGetSymbolAddress((void**)&p_encproj, g_enc_proj);
    cudaGetSymbolAddress((void**)&p_gates, g_gates);
    cudaGetSymbolAddress((void**)&p_comb, g_comb);
    cudaGetSymbolAddress((void**)&p_h1, g_h1);
    cudaGetSymbolAddress((void**)&p_c1, g_c1);
    cudaGetSymbolAddress((void**)&p_h2, g_h2);
    cudaGetSymbolAddress((void**)&p_c2, g_c2);
    cudaGetSymbolAddress((void**)&p_o0, g_o0);
    cudaGetSymbolAddress((void**)&p_e, g_e);
    cudaGetSymbolAddress((void**)&p_alpha, g_alpha);
    cudaGetSymbolAddress((void**)&p_at, g_at);

    // init states
    init_k<<<(BB * HH + 255) / 256, 256>>>(h1i, c1i, h2i, c2i);

    // precompute enc_proj = enc_hiddens @ W_att^T + b_att  (M = B*L = 8192)
    gemm_mp<<<dim3(HH / 64, (BB * LL) / 64, 1), 256>>>(
        enc, HEE, W_att, HEE, HEE,
        nullptr, 0, nullptr, 0, 0,
        nullptr, 0, nullptr, 0, 0,
        b_att, nullptr,
        p_encproj, HH, 0, 1, 0);

    for (int t = 0; t < TT; ++t) {
        const float* x_t = cap + (size_t)t * BB * EE;
        const float* o_prev = (t == 0) ? p_o0 : (outs + (size_t)(t - 1) * BB * HH);

        // gates1 = x_t @ W_ih1^T + h1 @ W_hh1^T + b  (split-K x4 partials)
        gemm_mp<<<dim3(4 * HH / 64, 1, 4), 256>>>(
            x_t, EE, W_ih1, EE, EE,
            p_h1, HH, W_hh1, HH, HH,
            nullptr, 0, nullptr, 0, 0,
            b_ih1, b_hh1,
            p_gates, 4 * HH, BB * 4 * HH, 4, 2);
        lstm_pw<<<(BB * HH) / 256, 256>>>(p_gates, 4, p_h1, p_c1);

        // gates2 = [h1, o_prev] @ W_ih2^T + h2 @ W_hh2^T + b
        gemm_mp<<<dim3(4 * HH / 64, 1, 4), 256>>>(
            p_h1, HH, W_ih2, 2 * HH, HH,
            o_prev, HH, W_ih2 + HH, 2 * HH, HH,
            p_h2, HH, W_hh2, HH, HH,
            b_ih2, b_hh2,
            p_gates, 4 * HH, BB * 4 * HH, 4, 2);
        lstm_pw<<<(BB * HH) / 256, 256>>>(p_gates, 4, p_h2, p_c2);

        // attention
        scores_k<<<dim3(LL / 16, BB), 256>>>(p_h2, masks, p_encproj, p_e);
        softmax_k<<<BB, LL>>>(p_e, p_alpha);
        attnout_k<<<dim3(HEE / 128, BB), 128>>>(p_alpha, enc, p_at);

        // o_t = tanh([a_t, h2] @ W_comb^T + b_comb)  (split-K x8 partials)
        gemm_mp<<<dim3(HH / 64, 1, 8), 256>>>(
            p_at, HEE, W_comb, HEE + HH, HEE,
            p_h2, HH, W_comb + HEE, HEE + HH, HH,
            nullptr, 0, nullptr, 0, 0,
            b_comb, nullptr,
            p_comb, HH, BB * HH, 8, 2);
        finish_k<<<(BB * HH) / 256, 256>>>(p_comb, 8, outs + (size_t)t * BB * HH);
    }
}